// round 4
// baseline (speedup 1.0000x reference)
#include <cuda_runtime.h>
#include <cuda_bf16.h>
#include <cstdint>

#define B_   256
#define P_   4
#define D_   768
#define U_   32
#define IN_  3072

#define BM 256
#define BN 64
#define BK 16
#define NTILES (IN_ / BK)   // 192
#define THREADS 256
#define STAGES 4

// smem per stage (bytes): A_hi[16][264]bf16=8448 | A_lo 8448 | B_hi[16][72]bf16=2304 | B_lo 2304
#define A_STRIDE 264           // bf16 elems per k-row (528B, 4-bank offset mod 32)
#define B_STRIDE 72            // 144B
#define ST_AH 0
#define ST_AL 8448
#define ST_BH 16896
#define ST_BL 19200
#define STAGE_SZ 21504
#define SMEM_TOTAL (STAGES * STAGE_SZ)   // 86016

// Pre-converted A, K-major: [IN_][B_] bf16, hi/lo planes (1.5MB each)
__device__ __align__(16) __nv_bfloat16 g_Ahi[IN_ * B_];
__device__ __align__(16) __nv_bfloat16 g_Alo[IN_ * B_];

__device__ __forceinline__ uint32_t smem_u32(const void* p) {
    uint32_t a;
    asm("{ .reg .u64 t; cvta.to.shared.u64 t, %1; cvt.u32.u64 %0, t; }" : "=r"(a) : "l"(p));
    return a;
}
#define CP_ASYNC16(dst, src) \
    asm volatile("cp.async.cg.shared.global [%0], [%1], 16;" :: "r"(dst), "l"(src))
#define CP_COMMIT() asm volatile("cp.async.commit_group;" ::: "memory")
#define CP_WAIT2()  asm volatile("cp.async.wait_group 2;" ::: "memory")
#define CP_WAIT0()  asm volatile("cp.async.wait_group 0;" ::: "memory")

#define LDSM_X4T(r, addr) \
    asm volatile("ldmatrix.sync.aligned.m8n8.x4.trans.shared.b16 {%0,%1,%2,%3}, [%4];" \
        : "=r"((r)[0]), "=r"((r)[1]), "=r"((r)[2]), "=r"((r)[3]) : "r"(addr))

#define MMA16816(d, a, b0, b1) \
    asm volatile("mma.sync.aligned.m16n8k16.row.col.f32.bf16.bf16.f32 " \
        "{%0,%1,%2,%3}, {%4,%5,%6,%7}, {%8,%9}, {%0,%1,%2,%3};" \
        : "+f"((d)[0]), "+f"((d)[1]), "+f"((d)[2]), "+f"((d)[3]) \
        : "r"((a)[0]), "r"((a)[1]), "r"((a)[2]), "r"((a)[3]), "r"(b0), "r"(b1))

__device__ __forceinline__ uint32_t pack2(__nv_bfloat16 a, __nv_bfloat16 b) {
    return (uint32_t)__bfloat16_as_ushort(a) | ((uint32_t)__bfloat16_as_ushort(b) << 16);
}
__device__ __forceinline__ void cvt_hilo(float x, float y, uint32_t& hi, uint32_t& lo) {
    __nv_bfloat16 hx = __float2bfloat16(x);
    __nv_bfloat16 hy = __float2bfloat16(y);
    __nv_bfloat16 lx = __float2bfloat16(x - __bfloat162float(hx));
    __nv_bfloat16 ly = __float2bfloat16(y - __bfloat162float(hy));
    hi = pack2(hx, hy);
    lo = pack2(lx, ly);
}

// ---------------- Pre-pass: A fp32 [256][3072] -> K-major bf16 hi/lo [3072][256] ----------------
__global__ void coldprompt_prep(const float* __restrict__ A)
{
    __shared__ float T[32][37];
    const int tid = threadIdx.x;
    const int k0 = blockIdx.x * 32;
    const int b0 = blockIdx.y * 32;

    {   // load 32(b) x 32(k), store transposed into T[k][b]
        const int bb  = tid >> 3;
        const int kk4 = (tid & 7) * 4;
        float4 v = *(const float4*)(A + (size_t)(b0 + bb) * IN_ + k0 + kk4);
        T[kk4 + 0][bb] = v.x;
        T[kk4 + 1][bb] = v.y;
        T[kk4 + 2][bb] = v.z;
        T[kk4 + 3][bb] = v.w;
    }
    __syncthreads();
    {   // write out [k][b] bf16 hi/lo
        const int kk  = tid >> 3;
        const int bb4 = (tid & 7) * 4;
        float x0 = T[kk][bb4 + 0], x1 = T[kk][bb4 + 1];
        float x2 = T[kk][bb4 + 2], x3 = T[kk][bb4 + 3];
        uint32_t h0, l0, h1, l1;
        cvt_hilo(x0, x1, h0, l0);
        cvt_hilo(x2, x3, h1, l1);
        const size_t o = (size_t)(k0 + kk) * B_ + b0 + bb4;
        *(uint2*)(g_Ahi + o) = make_uint2(h0, h1);
        *(uint2*)(g_Alo + o) = make_uint2(l0, l1);
    }
}

// ---------------- Main GEMM ----------------
__global__ void __launch_bounds__(THREADS, 1)
coldprompt_mma_gemm(const float* __restrict__ W,     // [32, 3072, 768]
                    const float* __restrict__ bias,  // [32, 768]
                    float* __restrict__ C)           // [32*256, 768]
{
    extern __shared__ char smem[];
    const uint32_t sb = smem_u32(smem);

    const int tid  = threadIdx.x;
    const int wid  = tid >> 5;
    const int lane = tid & 31;
    const int u    = blockIdx.x & 31;
    const int n0   = (blockIdx.x >> 5) * BN;

    const int wm = (wid & 3) * 64;    // 4 m-warps
    const int wn = (wid >> 2) * 32;   // 2 n-warps

    const float* __restrict__ Wbase = W + (size_t)u * IN_ * D_ + n0;

    // cp.async A mapping: 2 chunks of 16B per plane per thread
    const int ar0 = tid >> 5;                 // k-row 0..7
    const int ac  = (tid & 31) * 16;          // byte offset within 512B row data
    // B LDG mapping: 1 float4 per thread
    const int bkr = tid >> 4;                 // k-row 0..15
    const int bn4 = (tid & 15) * 4;           // n offset

    float acc[4][4][4];
    #pragma unroll
    for (int i = 0; i < 4; i++)
        #pragma unroll
        for (int j = 0; j < 4; j++) {
            acc[i][j][0] = 0.f; acc[i][j][1] = 0.f;
            acc[i][j][2] = 0.f; acc[i][j][3] = 0.f;
        }

    float4 breg[3];

    auto ISSUE_A = [&](int it) {
        const int s = it & (STAGES - 1);
        const uint32_t st = sb + s * STAGE_SZ;
        const size_t gk = (size_t)it * BK * B_;   // element offset of k-row block
        #pragma unroll
        for (int h = 0; h < 2; ++h) {
            const int r = ar0 + h * 8;
            const uint32_t doff = r * (A_STRIDE * 2) + ac;
            const char* srch = (const char*)(g_Ahi + gk + (size_t)r * B_) + ac;
            const char* srcl = (const char*)(g_Alo + gk + (size_t)r * B_) + ac;
            CP_ASYNC16(st + ST_AH + doff, srch);
            CP_ASYNC16(st + ST_AL + doff, srcl);
        }
        CP_COMMIT();
    };
    auto LDG_B = [&](int it, float4& r) {
        r = *(const float4*)(Wbase + (size_t)(it * BK + bkr) * D_ + bn4);
    };
    auto STS_B = [&](int it, const float4& v) {
        const int s = it & (STAGES - 1);
        char* st = smem + s * STAGE_SZ;
        uint32_t h0, l0, h1, l1;
        cvt_hilo(v.x, v.y, h0, l0);
        cvt_hilo(v.z, v.w, h1, l1);
        const uint32_t o = bkr * (B_STRIDE * 2) + bn4 * 2;
        *(uint2*)(st + ST_BH + o) = make_uint2(h0, h1);
        *(uint2*)(st + ST_BL + o) = make_uint2(l0, l1);
    };

    // ldmatrix lane address components
    const uint32_t a_krow = (lane & 7) + ((lane >> 4) & 1) * 8;
    const uint32_t a_mcol = ((lane >> 3) & 1) * 8;
    const uint32_t b_krow = (lane & 7) + ((lane >> 3) & 1) * 8;
    const uint32_t b_ncol = (lane >> 4) * 8;

    auto COMPUTE = [&](int it) {
        const uint32_t st = sb + (it & (STAGES - 1)) * STAGE_SZ;
        uint32_t a_hi[4][4], a_lo[4][4];
        #pragma unroll
        for (int mt = 0; mt < 4; ++mt) {
            const uint32_t ao = a_krow * (A_STRIDE * 2) + (wm + mt * 16 + a_mcol) * 2;
            LDSM_X4T(a_hi[mt], st + ST_AH + ao);
            LDSM_X4T(a_lo[mt], st + ST_AL + ao);
        }
        uint32_t b_hi[8], b_lo[8];
        #pragma unroll
        for (int nt2 = 0; nt2 < 2; ++nt2) {
            const uint32_t bo = b_krow * (B_STRIDE * 2) + (wn + nt2 * 16 + b_ncol) * 2;
            LDSM_X4T(&b_hi[nt2 * 4], st + ST_BH + bo);
            LDSM_X4T(&b_lo[nt2 * 4], st + ST_BL + bo);
        }
        #pragma unroll
        for (int mt = 0; mt < 4; ++mt)
            #pragma unroll
            for (int nt = 0; nt < 4; ++nt) {
                MMA16816(acc[mt][nt], a_hi[mt], b_hi[nt * 2], b_hi[nt * 2 + 1]);
                MMA16816(acc[mt][nt], a_hi[mt], b_lo[nt * 2], b_lo[nt * 2 + 1]);
                MMA16816(acc[mt][nt], a_lo[mt], b_hi[nt * 2], b_hi[nt * 2 + 1]);
            }
    };

    // ---- prologue: prefetch 3 stages ----
    LDG_B(0, breg[0]); ISSUE_A(0);
    LDG_B(1, breg[1]); ISSUE_A(1);
    LDG_B(2, breg[2]); ISSUE_A(2);
    STS_B(0, breg[0]);
    CP_WAIT2();
    __syncthreads();

    #pragma unroll 1
    for (int it = 0; it < NTILES; ++it) {
        if (it + 3 < NTILES) {
            LDG_B(it + 3, breg[(it + 3) % 3]);
            ISSUE_A(it + 3);
        } else {
            CP_COMMIT();   // keep group count uniform for wait_group<2>
        }
        if (it + 1 < NTILES) STS_B(it + 1, breg[(it + 1) % 3]);
        CP_WAIT2();
        __syncthreads();
        COMPUTE(it);
    }

    // ---- epilogue ----
    const int g  = lane >> 2;
    const int tq = lane & 3;
    #pragma unroll
    for (int mt = 0; mt < 4; ++mt) {
        #pragma unroll
        for (int nt = 0; nt < 4; ++nt) {
            const int row0 = wm + mt * 16 + g;
            const int col  = n0 + wn + nt * 8 + tq * 2;
            const float2 bv = *(const float2*)(bias + (size_t)u * D_ + col);
            float* c0 = C + ((size_t)u * B_ + row0) * D_ + col;
            float* c1 = c0 + (size_t)8 * D_;
            float2 o0, o1;
            o0.x = acc[mt][nt][0] + bv.x;
            o0.y = acc[mt][nt][1] + bv.y;
            o1.x = acc[mt][nt][2] + bv.x;
            o1.y = acc[mt][nt][3] + bv.y;
            *(float2*)c0 = o0;
            *(float2*)c1 = o1;
        }
    }
}

// ---------------- mean_emb ----------------
__global__ void coldprompt_mean(const float* __restrict__ w, float* __restrict__ out)
{
    const int n4 = (B_ * D_) / 4;
    int i = blockIdx.x * blockDim.x + threadIdx.x;
    if (i >= n4) return;
    const int d4_per_row = D_ / 4;
    const int b  = i / d4_per_row;
    const int d4 = i % d4_per_row;
    const float4* wp = (const float4*)w;
    float4 s = make_float4(0.f, 0.f, 0.f, 0.f);
    #pragma unroll
    for (int p = 0; p < P_; p++) {
        float4 v = wp[(size_t)(b * P_ + p) * d4_per_row + d4];
        s.x += v.x; s.y += v.y; s.z += v.z; s.w += v.w;
    }
    s.x *= 0.25f; s.y *= 0.25f; s.z *= 0.25f; s.w *= 0.25f;
    ((float4*)out)[i] = s;
}

extern "C" void kernel_launch(void* const* d_in, const int* in_sizes, int n_in,
                              void* d_out, int out_size)
{
    const float* weight = (const float*)d_in[0];
    const float* W_spec = (const float*)d_in[1];
    const float* b_spec = (const float*)d_in[2];
    float* out = (float*)d_out;

    cudaFuncSetAttribute(coldprompt_mma_gemm,
                         cudaFuncAttributeMaxDynamicSharedMemorySize, SMEM_TOTAL);

    // order: mean, prep, gemm (so ncu -s 5 -c 1 lands on the GEMM)
    const int n4 = (B_ * D_) / 4;
    coldprompt_mean<<<(n4 + 255) / 256, 256>>>(weight, out + (size_t)U_ * B_ * D_);

    dim3 pgrid(IN_ / 32, B_ / 32);   // (96, 8)
    coldprompt_prep<<<pgrid, 256>>>(weight);

    dim3 grid(U_ * (D_ / BN));       // 32*12 = 384, u = bx&31, ntile = bx>>5
    coldprompt_mma_gemm<<<grid, THREADS, SMEM_TOTAL>>>(W_spec, b_spec, out);
}

// round 5
// speedup vs baseline: 1.8278x; 1.8278x over previous
#include <cuda_runtime.h>
#include <cuda_bf16.h>
#include <cstdint>

#define B_   256
#define P_   4
#define D_   768
#define U_   32
#define IN_  3072

#define BM 128
#define BN 128
#define BK 32
#define NTILES (IN_ / BK)   // 96
#define THREADS 256

// smem per stage (bytes): rows are 136 bf16 = 272B (conflict-free for ldmatrix trans)
#define ROW_B   272
#define ST_AH   0
#define ST_AL   (32 * ROW_B)        // 8704
#define ST_BH   (2 * 32 * ROW_B)    // 17408
#define ST_BL   (3 * 32 * ROW_B)    // 26112
#define STAGE_SZ (4 * 32 * ROW_B)   // 34816
#define SMEM_TOTAL (2 * STAGE_SZ)   // 69632

// Pre-converted A, K-major: [IN_][B_] bf16 hi/lo planes (1.5MB each, reused 192x)
__device__ __align__(16) __nv_bfloat16 g_Ahi[IN_ * B_];
__device__ __align__(16) __nv_bfloat16 g_Alo[IN_ * B_];

__device__ __forceinline__ uint32_t smem_u32(const void* p) {
    uint32_t a;
    asm("{ .reg .u64 t; cvta.to.shared.u64 t, %1; cvt.u32.u64 %0, t; }" : "=r"(a) : "l"(p));
    return a;
}
#define LDSM_X4T(r, addr) \
    asm volatile("ldmatrix.sync.aligned.m8n8.x4.trans.shared.b16 {%0,%1,%2,%3}, [%4];" \
        : "=r"((r)[0]), "=r"((r)[1]), "=r"((r)[2]), "=r"((r)[3]) : "r"(addr))
#define MMA16816(d, a, b0, b1) \
    asm volatile("mma.sync.aligned.m16n8k16.row.col.f32.bf16.bf16.f32 " \
        "{%0,%1,%2,%3}, {%4,%5,%6,%7}, {%8,%9}, {%0,%1,%2,%3};" \
        : "+f"((d)[0]), "+f"((d)[1]), "+f"((d)[2]), "+f"((d)[3]) \
        : "r"((a)[0]), "r"((a)[1]), "r"((a)[2]), "r"((a)[3]), "r"(b0), "r"(b1))

__device__ __forceinline__ uint32_t pack2(__nv_bfloat16 a, __nv_bfloat16 b) {
    return (uint32_t)__bfloat16_as_ushort(a) | ((uint32_t)__bfloat16_as_ushort(b) << 16);
}
__device__ __forceinline__ void cvt_hilo(float x, float y, uint32_t& hi, uint32_t& lo) {
    __nv_bfloat16 hx = __float2bfloat16(x);
    __nv_bfloat16 hy = __float2bfloat16(y);
    __nv_bfloat16 lx = __float2bfloat16(x - __bfloat162float(hx));
    __nv_bfloat16 ly = __float2bfloat16(y - __bfloat162float(hy));
    hi = pack2(hx, hy);
    lo = pack2(lx, ly);
}

// ---------------- Pre-pass: A fp32 [256][3072] -> K-major bf16 hi/lo [3072][256] ----------------
__global__ void coldprompt_prep(const float* __restrict__ A)
{
    __shared__ float T[32][37];
    const int tid = threadIdx.x;
    const int k0 = blockIdx.x * 32;
    const int b0 = blockIdx.y * 32;
    {
        const int bb  = tid >> 3;
        const int kk4 = (tid & 7) * 4;
        float4 v = *(const float4*)(A + (size_t)(b0 + bb) * IN_ + k0 + kk4);
        T[kk4 + 0][bb] = v.x;
        T[kk4 + 1][bb] = v.y;
        T[kk4 + 2][bb] = v.z;
        T[kk4 + 3][bb] = v.w;
    }
    __syncthreads();
    {
        const int kk  = tid >> 3;
        const int bb4 = (tid & 7) * 4;
        float x0 = T[kk][bb4 + 0], x1 = T[kk][bb4 + 1];
        float x2 = T[kk][bb4 + 2], x3 = T[kk][bb4 + 3];
        uint32_t h0, l0, h1, l1;
        cvt_hilo(x0, x1, h0, l0);
        cvt_hilo(x2, x3, h1, l1);
        const size_t o = (size_t)(k0 + kk) * B_ + b0 + bb4;
        *(uint2*)(g_Ahi + o) = make_uint2(h0, h1);
        *(uint2*)(g_Alo + o) = make_uint2(l0, l1);
    }
}

// ---------------- Main GEMM ----------------
__global__ void __launch_bounds__(THREADS, 1)
coldprompt_mma_gemm(const float* __restrict__ W,     // [32, 3072, 768]
                    const float* __restrict__ bias,  // [32, 768]
                    float* __restrict__ C)           // [32*256, 768]
{
    extern __shared__ char smem[];
    const uint32_t sb = smem_u32(smem);

    const int tid  = threadIdx.x;
    const int wid  = tid >> 5;
    const int lane = tid & 31;
    const int u    = blockIdx.z;
    const int m0   = blockIdx.y * BM;
    const int n0   = blockIdx.x * BN;

    const int wm = (wid >> 2) * 64;   // 2 m-warps of 64
    const int wn = (wid & 3) * 32;    // 4 n-warps of 32

    const float* __restrict__ Wbase = W + (size_t)u * IN_ * D_ + n0;

    // A copy mapping: per plane 2 chunks of 16B
    const int a_row0 = tid >> 4;            // k-row 0..15 (chunk0), +16 (chunk1)
    const int a_c8   = (tid & 15) * 8;      // elem offset in m (8 bf16 = 16B)
    // B load mapping: 4 chunks of float4
    const int b_kr0 = tid >> 5;             // 0..7 (+8c)
    const int b_n4  = (tid & 31) * 4;

    float acc[4][4][4];
    #pragma unroll
    for (int i = 0; i < 4; i++)
        #pragma unroll
        for (int j = 0; j < 4; j++) {
            acc[i][j][0] = 0.f; acc[i][j][1] = 0.f;
            acc[i][j][2] = 0.f; acc[i][j][3] = 0.f;
        }

    uint4  areg_h[2], areg_l[2];
    float4 breg[4];

    auto LOAD = [&](int it) {
        const int k0 = it * BK;
        #pragma unroll
        for (int c = 0; c < 2; ++c) {
            const int kr = a_row0 + c * 16;
            const size_t o = (size_t)(k0 + kr) * B_ + m0 + a_c8;
            areg_h[c] = *(const uint4*)(g_Ahi + o);
            areg_l[c] = *(const uint4*)(g_Alo + o);
        }
        #pragma unroll
        for (int c = 0; c < 4; ++c) {
            const int kr = b_kr0 + c * 8;
            breg[c] = *(const float4*)(Wbase + (size_t)(k0 + kr) * D_ + b_n4);
        }
    };

    auto STORE = [&](int s) {
        char* st = smem + s * STAGE_SZ;
        #pragma unroll
        for (int c = 0; c < 2; ++c) {
            const int kr = a_row0 + c * 16;
            char* p = st + kr * ROW_B + a_c8 * 2;
            *(uint4*)(p + ST_AH) = areg_h[c];
            *(uint4*)(p + ST_AL) = areg_l[c];
        }
        #pragma unroll
        for (int c = 0; c < 4; ++c) {
            const int kr = b_kr0 + c * 8;
            uint32_t h0, l0, h1, l1;
            cvt_hilo(breg[c].x, breg[c].y, h0, l0);
            cvt_hilo(breg[c].z, breg[c].w, h1, l1);
            char* p = st + kr * ROW_B + b_n4 * 2;
            *(uint2*)(p + ST_BH) = make_uint2(h0, h1);
            *(uint2*)(p + ST_BL) = make_uint2(l0, l1);
        }
    };

    // ldmatrix lane address components
    const uint32_t a_krow = (lane & 7) + ((lane >> 4) & 1) * 8;
    const uint32_t a_mcol = ((lane >> 3) & 1) * 8;
    const uint32_t b_krow = (lane & 7) + ((lane >> 3) & 1) * 8;
    const uint32_t b_ncol = (lane >> 4) * 8;

    auto COMPUTE = [&](int s) {
        const uint32_t st = sb + s * STAGE_SZ;
        #pragma unroll
        for (int ks = 0; ks < 2; ++ks) {
            uint32_t a_hi[4][4], a_lo[4][4];
            #pragma unroll
            for (int mt = 0; mt < 4; ++mt) {
                const uint32_t ao =
                    (ks * 16 + a_krow) * ROW_B + (wm + mt * 16 + a_mcol) * 2;
                LDSM_X4T(a_hi[mt], st + ST_AH + ao);
                LDSM_X4T(a_lo[mt], st + ST_AL + ao);
            }
            uint32_t b_hi[8], b_lo[8];
            #pragma unroll
            for (int nt2 = 0; nt2 < 2; ++nt2) {
                const uint32_t bo =
                    (ks * 16 + b_krow) * ROW_B + (wn + nt2 * 16 + b_ncol) * 2;
                LDSM_X4T(&b_hi[nt2 * 4], st + ST_BH + bo);
                LDSM_X4T(&b_lo[nt2 * 4], st + ST_BL + bo);
            }
            #pragma unroll
            for (int mt = 0; mt < 4; ++mt)
                #pragma unroll
                for (int nt = 0; nt < 4; ++nt) {
                    MMA16816(acc[mt][nt], a_hi[mt], b_hi[nt * 2], b_hi[nt * 2 + 1]);
                    MMA16816(acc[mt][nt], a_hi[mt], b_lo[nt * 2], b_lo[nt * 2 + 1]);
                    MMA16816(acc[mt][nt], a_lo[mt], b_hi[nt * 2], b_hi[nt * 2 + 1]);
                }
        }
    };

    // ---- pipeline (R3 structure) ----
    LOAD(0);
    STORE(0);
    __syncthreads();

    #pragma unroll 1
    for (int it = 0; it < NTILES; ++it) {
        if (it + 1 < NTILES) LOAD(it + 1);
        COMPUTE(it & 1);
        if (it + 1 < NTILES) {
            __syncthreads();
            STORE((it + 1) & 1);
            __syncthreads();
        }
    }

    // ---- epilogue ----
    const int g  = lane >> 2;
    const int tq = lane & 3;
    #pragma unroll
    for (int mt = 0; mt < 4; ++mt) {
        #pragma unroll
        for (int nt = 0; nt < 4; ++nt) {
            const int row0 = m0 + wm + mt * 16 + g;
            const int col  = n0 + wn + nt * 8 + tq * 2;
            const float2 bv = *(const float2*)(bias + (size_t)u * D_ + col);
            float* c0 = C + ((size_t)u * B_ + row0) * D_ + col;
            float* c1 = c0 + (size_t)8 * D_;
            float2 o0, o1;
            o0.x = acc[mt][nt][0] + bv.x;
            o0.y = acc[mt][nt][1] + bv.y;
            o1.x = acc[mt][nt][2] + bv.x;
            o1.y = acc[mt][nt][3] + bv.y;
            *(float2*)c0 = o0;
            *(float2*)c1 = o1;
        }
    }
}

// ---------------- mean_emb ----------------
__global__ void coldprompt_mean(const float* __restrict__ w, float* __restrict__ out)
{
    const int n4 = (B_ * D_) / 4;
    int i = blockIdx.x * blockDim.x + threadIdx.x;
    if (i >= n4) return;
    const int d4_per_row = D_ / 4;
    const int b  = i / d4_per_row;
    const int d4 = i % d4_per_row;
    const float4* wp = (const float4*)w;
    float4 s = make_float4(0.f, 0.f, 0.f, 0.f);
    #pragma unroll
    for (int p = 0; p < P_; p++) {
        float4 v = wp[(size_t)(b * P_ + p) * d4_per_row + d4];
        s.x += v.x; s.y += v.y; s.z += v.z; s.w += v.w;
    }
    s.x *= 0.25f; s.y *= 0.25f; s.z *= 0.25f; s.w *= 0.25f;
    ((float4*)out)[i] = s;
}

extern "C" void kernel_launch(void* const* d_in, const int* in_sizes, int n_in,
                              void* d_out, int out_size)
{
    const float* weight = (const float*)d_in[0];
    const float* W_spec = (const float*)d_in[1];
    const float* b_spec = (const float*)d_in[2];
    float* out = (float*)d_out;

    cudaFuncSetAttribute(coldprompt_mma_gemm,
                         cudaFuncAttributeMaxDynamicSharedMemorySize, SMEM_TOTAL);

    const int n4 = (B_ * D_) / 4;
    coldprompt_mean<<<(n4 + 255) / 256, 256>>>(weight, out + (size_t)U_ * B_ * D_);

    dim3 pgrid(IN_ / 32, B_ / 32);   // (96, 8)
    coldprompt_prep<<<pgrid, 256>>>(weight);

    dim3 grid(D_ / BN, B_ / BM, U_);   // (6, 2, 32)
    coldprompt_mma_gemm<<<grid, THREADS, SMEM_TOTAL>>>(W_spec, b_spec, out);
}